// round 5
// baseline (speedup 1.0000x reference)
#include <cuda_runtime.h>
#include <stdint.h>

#define NN 100000
#define EE 3200000
#define INC 495
#define HC 16
#define NB 391            // ceil(NN/256)

// ---------------- static device scratch ----------------
__device__ __align__(16) float g_dis[NN];
__device__ int   g_cnt[NN];
__device__ int   g_off[NN + 1];
__device__ int   g_cur[NN];
__device__ int   g_csr[EE];
__device__ int   g_src[EE];
__device__ int   g_dst[EE];
__device__ int   g_bsum[NB];
__device__ int   g_bpre[NB];
__device__ __align__(16) float g_Tbuf[2][NN * HC];  // double-buffered node features (pre-scaled by dis)
__device__ __align__(16) float g_B[NN * HC];        // head "B" table
__device__ int   g_is64;

// ---------------- init: zero counts + dtype detect ----------------
__global__ __launch_bounds__(256) void k_init(const unsigned int* __restrict__ w) {
    int i = blockIdx.x * blockDim.x + threadIdx.x;
    if (i < NN) g_cnt[i] = 0;
    if (blockIdx.x == 0) {
        __shared__ unsigned int s_or;
        if (threadIdx.x == 0) s_or = 0u;
        __syncthreads();
        unsigned int v = 0u;
        for (int k = threadIdx.x; k < 4096; k += blockDim.x)
            v |= w[2 * k + 1];
        atomicOr(&s_or, v);
        __syncthreads();
        if (threadIdx.x == 0) g_is64 = (s_or == 0u) ? 1 : 0;
    }
}

__global__ __launch_bounds__(256) void k_edge_prep(const void* __restrict__ ei_raw) {
    int e = blockIdx.x * blockDim.x + threadIdx.x;
    if (e >= EE) return;
    int s, d;
    if (g_is64) {
        const long long* ei = (const long long*)ei_raw;
        s = (int)ei[e];
        d = (int)ei[EE + e];
    } else {
        const int* ei = (const int*)ei_raw;
        s = ei[e];
        d = ei[EE + e];
    }
    g_src[e] = s;
    g_dst[e] = d;
    atomicAdd(&g_cnt[d], 1);
}

// ---- hierarchical scan ----
__global__ __launch_bounds__(256) void k_partial() {
    __shared__ int sh[256];
    int i = blockIdx.x * 256 + threadIdx.x;
    sh[threadIdx.x] = (i < NN) ? g_cnt[i] : 0;
    __syncthreads();
#pragma unroll
    for (int off = 128; off > 0; off >>= 1) {
        if (threadIdx.x < off) sh[threadIdx.x] += sh[threadIdx.x + off];
        __syncthreads();
    }
    if (threadIdx.x == 0) g_bsum[blockIdx.x] = sh[0];
}

__global__ __launch_bounds__(512) void k_scan_bsum() {
    __shared__ int sh[512];
    int t = threadIdx.x;
    sh[t] = (t < NB) ? g_bsum[t] : 0;
    __syncthreads();
#pragma unroll
    for (int off = 1; off < 512; off <<= 1) {
        int v = (t >= off) ? sh[t - off] : 0;
        __syncthreads();
        sh[t] += v;
        __syncthreads();
    }
    if (t < NB) g_bpre[t] = (t == 0) ? 0 : sh[t - 1];
}

__global__ __launch_bounds__(256) void k_offsets() {
    __shared__ int sh[256];
    int t = threadIdx.x;
    int i = blockIdx.x * 256 + t;
    int c = (i < NN) ? g_cnt[i] : 0;
    sh[t] = c;
    __syncthreads();
#pragma unroll
    for (int off = 1; off < 256; off <<= 1) {
        int v = (t >= off) ? sh[t - off] : 0;
        __syncthreads();
        sh[t] += v;
        __syncthreads();
    }
    if (i < NN) {
        int excl = g_bpre[blockIdx.x] + sh[t] - c;
        g_off[i] = excl;
        g_cur[i] = excl;
        g_dis[i] = rsqrtf((float)(c + 1));
    }
    if (i == NN - 1) g_off[NN] = EE;
}

__global__ __launch_bounds__(256) void k_fill() {
    int e = blockIdx.x * blockDim.x + threadIdx.x;
    if (e >= EE) return;
    int d = g_dst[e];
    int pos = atomicAdd(&g_cur[d], 1);
    g_csr[pos] = g_src[e];
}

// ---------------- layer 0 dense: Tbuf[0] = (x @ W0) * dis ----------------
__global__ __launch_bounds__(256) void k_dense0(const float* __restrict__ x,
                                                const float* __restrict__ W0) {
    __shared__ float sW[INC * 17];
    for (int idx = threadIdx.x; idx < INC * HC; idx += 256) {
        int c = idx >> 4, j = idx & 15;
        sW[c * 17 + j] = W0[idx];
    }
    __syncthreads();

    int warp = threadIdx.x >> 5;
    int lane = threadIdx.x & 31;
    int r0 = (blockIdx.x * 8 + warp) * 4;
    if (r0 >= NN) return;

    float acc[4][16];
#pragma unroll
    for (int i = 0; i < 4; i++)
#pragma unroll
        for (int j = 0; j < 16; j++) acc[i][j] = 0.0f;

    for (int c = lane; c < INC; c += 32) {
        float xv[4];
#pragma unroll
        for (int i = 0; i < 4; i++) {
            int r = r0 + i;
            xv[i] = (r < NN) ? __ldg(&x[(size_t)r * INC + c]) : 0.0f;
        }
#pragma unroll
        for (int j = 0; j < 16; j++) {
            float w = sW[c * 17 + j];
#pragma unroll
            for (int i = 0; i < 4; i++) acc[i][j] = fmaf(xv[i], w, acc[i][j]);
        }
    }

#pragma unroll
    for (int j = 0; j < 16; j++) {
#pragma unroll
        for (int i = 0; i < 4; i++) {
            float v = acc[i][j];
            v += __shfl_xor_sync(0xffffffffu, v, 16);
            v += __shfl_xor_sync(0xffffffffu, v, 8);
            v += __shfl_xor_sync(0xffffffffu, v, 4);
            v += __shfl_xor_sync(0xffffffffu, v, 2);
            v += __shfl_xor_sync(0xffffffffu, v, 1);
            if (lane == j) {
                int r = r0 + i;
                if (r < NN) g_Tbuf[0][r * 16 + j] = v * g_dis[r];
            }
        }
    }
}

// ---------------- fused aggregation + next dense (or head) ----------------
// warp per node; 8 groups of 4 lanes; each group gathers one 64B row / iter.
// HEAD=false: Tdst[i] = (relu(dis[i]*acc + b) @ W) * dis[i]
// HEAD=true : A(Tdst)  = relu(...)@W[0:16] + bf ;  g_B = relu(...)@W[16:32]
template <bool HEAD>
__global__ __launch_bounds__(256) void k_agg_fused(const float* __restrict__ b_in,
                                                   const float* __restrict__ W,
                                                   const float* __restrict__ bf,
                                                   int src_buf, int dst_buf) {
    constexpr int WSZ = HEAD ? 512 : 256;
    __shared__ float sW[WSZ];
    for (int idx = threadIdx.x; idx < WSZ; idx += 256) sW[idx] = W[idx];
    __syncthreads();

    int node = blockIdx.x * 8 + (threadIdx.x >> 5);
    if (node >= NN) return;
    int lane = threadIdx.x & 31;
    int grp = lane >> 2;       // 0..7
    int q = lane & 3;          // quarter (4 channels)

    const float4* T4 = (const float4*)g_Tbuf[src_buf];
    int beg = g_off[node];
    int end = g_off[node + 1];

    float4 acc = make_float4(0.f, 0.f, 0.f, 0.f);
    for (int e = beg + grp; e < end; e += 8) {
        int s = g_csr[e];
        float4 tv = __ldg(&T4[s * 4 + q]);
        acc.x += tv.x; acc.y += tv.y; acc.z += tv.z; acc.w += tv.w;
    }
    // self-loop (group 0 only, avoid duplication)
    if (grp == 0) {
        float4 tv = __ldg(&T4[node * 4 + q]);
        acc.x += tv.x; acc.y += tv.y; acc.z += tv.z; acc.w += tv.w;
    }
    // reduce across the 8 groups (lane bits 2..4)
#pragma unroll
    for (int off = 16; off >= 4; off >>= 1) {
        acc.x += __shfl_xor_sync(0xffffffffu, acc.x, off);
        acc.y += __shfl_xor_sync(0xffffffffu, acc.y, off);
        acc.z += __shfl_xor_sync(0xffffffffu, acc.z, off);
        acc.w += __shfl_xor_sync(0xffffffffu, acc.w, off);
    }
    float dsi = g_dis[node];
    const float4* b4 = (const float4*)b_in;
    float4 bb = __ldg(&b4[q]);
    float4 h;   // relu(H) for this quarter
    h.x = fmaxf(fmaf(dsi, acc.x, bb.x), 0.f);
    h.y = fmaxf(fmaf(dsi, acc.y, bb.y), 0.f);
    h.z = fmaxf(fmaf(dsi, acc.z, bb.z), 0.f);
    h.w = fmaxf(fmaf(dsi, acc.w, bb.w), 0.f);

    // broadcast full 16-channel relu(H) to every lane (quarters live in lanes 0..3)
    float hall[16];
#pragma unroll
    for (int sl = 0; sl < 4; sl++) {
        hall[sl * 4 + 0] = __shfl_sync(0xffffffffu, h.x, sl);
        hall[sl * 4 + 1] = __shfl_sync(0xffffffffu, h.y, sl);
        hall[sl * 4 + 2] = __shfl_sync(0xffffffffu, h.z, sl);
        hall[sl * 4 + 3] = __shfl_sync(0xffffffffu, h.w, sl);
    }

    int j = lane & 15;
    if (!HEAD) {
        float o = 0.f;
#pragma unroll
        for (int k = 0; k < 16; k++) o = fmaf(hall[k], sW[k * 16 + j], o);
        if (lane < 16) g_Tbuf[dst_buf][node * 16 + j] = o * dsi;  // pre-scale for next gather
    } else {
        float a = __ldg(&bf[j]);
        float bo = 0.f;
#pragma unroll
        for (int k = 0; k < 16; k++) {
            a  = fmaf(hall[k], sW[k * 16 + j], a);
            bo = fmaf(hall[k], sW[(16 + k) * 16 + j], bo);
        }
        if (lane < 16) {
            g_Tbuf[dst_buf][node * 16 + j] = a;   // A table
            g_B[node * 16 + j] = bo;              // B table
        }
    }
}

// ---------------- final per-edge output ----------------
__global__ __launch_bounds__(256) void k_edge_out(const float* __restrict__ Wf1,
                                                  const float* __restrict__ bf1,
                                                  float* __restrict__ out) {
    __shared__ float sW[16];
    __shared__ float sb1;
    if (threadIdx.x < 16) sW[threadIdx.x] = Wf1[threadIdx.x];
    if (threadIdx.x == 0) sb1 = bf1[0];
    __syncthreads();

    int e = blockIdx.x * blockDim.x + threadIdx.x;
    if (e >= EE) return;
    int s = g_src[e];
    int d = g_dst[e];
    const float4* ap = (const float4*)(g_Tbuf[1] + (size_t)s * 16);
    const float4* bp = (const float4*)(g_B + (size_t)d * 16);
    float sum = sb1;
#pragma unroll
    for (int qq = 0; qq < 4; qq++) {
        float4 av = __ldg(&ap[qq]);
        float4 bv = __ldg(&bp[qq]);
        sum = fmaf(fmaxf(av.x + bv.x, 0.0f), sW[qq * 4 + 0], sum);
        sum = fmaf(fmaxf(av.y + bv.y, 0.0f), sW[qq * 4 + 1], sum);
        sum = fmaf(fmaxf(av.z + bv.z, 0.0f), sW[qq * 4 + 2], sum);
        sum = fmaf(fmaxf(av.w + bv.w, 0.0f), sW[qq * 4 + 3], sum);
    }
    out[e] = sum;
}

// ---------------- launch ----------------
extern "C" void kernel_launch(void* const* d_in, const int* in_sizes, int n_in,
                              void* d_out, int out_size) {
    const float* x   = (const float*)d_in[0];
    const void*  ei  = d_in[1];
    const float* W0  = (const float*)d_in[2];
    const float* b0  = (const float*)d_in[3];
    const float* W1  = (const float*)d_in[4];
    const float* b1  = (const float*)d_in[5];
    const float* W2  = (const float*)d_in[6];
    const float* b2  = (const float*)d_in[7];
    const float* Wf0 = (const float*)d_in[8];
    const float* bf0 = (const float*)d_in[9];
    const float* Wf1 = (const float*)d_in[10];
    const float* bf1 = (const float*)d_in[11];
    float* out = (float*)d_out;

    const int TB = 256;
    const int gE = (EE + TB - 1) / TB;          // 12500
    const int gD0 = (NN + 31) / 32;             // 3125
    const int gA = (NN + 7) / 8;                // 12500 (warp per node)

    // CSR build
    k_init<<<NB, TB>>>((const unsigned int*)ei);
    k_edge_prep<<<gE, TB>>>(ei);
    k_partial<<<NB, TB>>>();
    k_scan_bsum<<<1, 512>>>();
    k_offsets<<<NB, TB>>>();
    k_fill<<<gE, TB>>>();

    // layer 0 dense
    k_dense0<<<gD0, TB>>>(x, W0);
    // agg(l0)+dense(l1) ; agg(l1)+dense(l2) ; agg(l2)+head
    k_agg_fused<false><<<gA, TB>>>(b0, W1, nullptr, 0, 1);
    k_agg_fused<false><<<gA, TB>>>(b1, W2, nullptr, 1, 0);
    k_agg_fused<true><<<gA, TB>>>(b2, Wf0, bf0, 0, 1);
    // edge head
    k_edge_out<<<gE, TB>>>(Wf1, bf1, out);
}